// round 8
// baseline (speedup 1.0000x reference)
#include <cuda_runtime.h>
#include <cuda.h>
#include <cuda_bf16.h>
#include <cstdint>

// ---------------------------------------------------------------------------
// Problem constants
// ---------------------------------------------------------------------------
#define BT 4096
#define HDIM 2048
#define VOCAB 32000
#define TILE_N 512                         // pair tile width (2 x N=256 cg2 MMAs)
#define K_CHUNK 64
#define N_KCHUNKS (HDIM / K_CHUNK)         // 32
#define M_PAIRS (BT / 256)                 // 16
#define N_TILES 63                         // 62 x 512 + 1 x 256 = 32000
#define IGNORE_INDEX (-100LL)
#define RL_BLOCKS 16
#define DEPTH 4                            // pipeline stages

// idesc kind::f16 cg2: dtype=F32, a/b=BF16, N=256 per MMA, M_total=256
#define MMA_IDESC ((1u << 4) | (1u << 7) | (1u << 10) | ((256 / 8) << 17) | ((256 / 16) << 24))

// SMEM layout per CTA: header, then DEPTH x (A 16KB) and DEPTH x (B 32KB)
#define SM_TMEMPTR 0
#define SM_FBAR(i) (8 + 8 * (i))           // 8..32
#define SM_MBAR(i) (40 + 8 * (i))          // 40..64
#define A_CHUNK_BYTES 16384                // 128 rows x 128B
#define B_BOX_BYTES   16384                // 128 rows x 128B
#define SM_A 1024                          // DEPTH x 16KB
#define SM_B (1024 + DEPTH * A_CHUNK_BYTES)              // 66560, DEPTH x 32KB
#define SM_TOTAL (SM_B + DEPTH * 2 * B_BOX_BYTES)        // 197632

#if defined(__CUDA_ARCH_FEAT_SM103_ALL) || defined(__CUDA_ARCH_FEAT_SM100_ALL)
#define HAS_TCGEN05 1
#else
#define HAS_TCGEN05 0
#endif

// ---------------------------------------------------------------------------
// Device scratch
// ---------------------------------------------------------------------------
__device__ __nv_bfloat16 g_hid_bf[(size_t)BT * HDIM];
__device__ __nv_bfloat16 g_w_bf[(size_t)VOCAB * HDIM];
__device__ float g_partials[(size_t)N_TILES * BT];
__device__ float g_tgt[BT];
__device__ float g_blocksum[RL_BLOCKS];
__device__ int   g_blockcnt[RL_BLOCKS];

// ---------------------------------------------------------------------------
// PTX helpers
// ---------------------------------------------------------------------------
__device__ __forceinline__ uint32_t smem_to_u32(const void* p) {
    uint32_t a;
    asm("{ .reg .u64 t; cvta.to.shared.u64 t, %1; cvt.u32.u64 %0, t; }" : "=r"(a) : "l"(p));
    return a;
}
__device__ __forceinline__ uint32_t cluster_ctarank_u32() {
    uint32_t r;
    asm("mov.u32 %0, %%cluster_ctarank;" : "=r"(r));
    return r;
}
#define TCGEN05_ALLOC_CG2(smem_addr, nCols) \
    asm volatile("tcgen05.alloc.cta_group::2.sync.aligned.shared::cta.b32 [%0], %1;" \
                 :: "r"((uint32_t)(smem_addr)), "r"((uint32_t)(nCols)) : "memory")
#define TCGEN05_DEALLOC_CG2(tmem_addr, nCols) \
    asm volatile("tcgen05.dealloc.cta_group::2.sync.aligned.b32 %0, %1;" :: "r"(tmem_addr), "r"((uint32_t)(nCols)))
#define TCGEN05_RELINQUISH_CG2() \
    asm volatile("tcgen05.relinquish_alloc_permit.cta_group::2.sync.aligned;")
#define TCGEN05_FENCE_AFTER() asm volatile("tcgen05.fence::after_thread_sync;" ::: "memory")
#define TCGEN05_FENCE_BEFORE() asm volatile("tcgen05.fence::before_thread_sync;" ::: "memory")
#define TCGEN05_WAIT_LD() asm volatile("tcgen05.wait::ld.sync.aligned;" ::: "memory")
#define MBARRIER_INIT(mbar, cnt) \
    asm volatile("mbarrier.init.shared.b64 [%0], %1;" :: "r"((uint32_t)(mbar)), "r"((uint32_t)(cnt)) : "memory")
#define MBARRIER_INVAL(mbar) \
    asm volatile("mbarrier.inval.shared.b64 [%0];" :: "r"((uint32_t)(mbar)) : "memory")
#define MBARRIER_EXPECT_TX(mbar, bytes) \
    asm volatile("mbarrier.arrive.expect_tx.shared.b64 _, [%0], %1;" \
                 :: "r"((uint32_t)(mbar)), "r"((uint32_t)(bytes)) : "memory")
#define CLUSTER_SYNC() do { \
    asm volatile("barrier.cluster.arrive.aligned;" ::: "memory"); \
    asm volatile("barrier.cluster.wait.aligned;" ::: "memory"); \
} while (0)
#define MBARRIER_WAIT_PARITY(mbar, parity) do {                                           \
    uint32_t _m = (uint32_t)(mbar); uint32_t _p = (uint32_t)(parity); uint32_t _d;        \
    asm volatile("{\n\t.reg .pred p;\n\t"                                                 \
        "mbarrier.try_wait.parity.acquire.cta.shared::cta.b64 p, [%1], %2;\n\t"           \
        "selp.b32 %0, 1, 0, p;\n\t}" : "=r"(_d) : "r"(_m), "r"(_p) : "memory");           \
    if (!_d) {                                                                            \
        asm volatile("{\n\t.reg .pred P1;\n\t"                                            \
            "WAIT_LOOP_%=:\n\t"                                                           \
            "mbarrier.try_wait.parity.acquire.cta.shared::cta.b64 P1, [%0], %1, 0x989680;\n\t" \
            "@P1 bra.uni WAIT_DONE_%=;\n\t"                                               \
            "bra.uni WAIT_LOOP_%=;\n\t"                                                   \
            "WAIT_DONE_%=:\n\t}" :: "r"(_m), "r"(_p) : "memory");                         \
    }                                                                                     \
} while (0)
#define TCGEN05_LD_32X32B_X32(r, tmem_addr) \
    asm volatile( \
        "tcgen05.ld.sync.aligned.32x32b.x32.b32 " \
        "{%0, %1, %2, %3, %4, %5, %6, %7, " \
        " %8, %9, %10, %11, %12, %13, %14, %15, " \
        " %16, %17, %18, %19, %20, %21, %22, %23, " \
        " %24, %25, %26, %27, %28, %29, %30, %31}, [%32];" \
        : "=r"((r)[0]),  "=r"((r)[1]),  "=r"((r)[2]),  "=r"((r)[3]), \
          "=r"((r)[4]),  "=r"((r)[5]),  "=r"((r)[6]),  "=r"((r)[7]), \
          "=r"((r)[8]),  "=r"((r)[9]),  "=r"((r)[10]), "=r"((r)[11]), \
          "=r"((r)[12]), "=r"((r)[13]), "=r"((r)[14]), "=r"((r)[15]), \
          "=r"((r)[16]), "=r"((r)[17]), "=r"((r)[18]), "=r"((r)[19]), \
          "=r"((r)[20]), "=r"((r)[21]), "=r"((r)[22]), "=r"((r)[23]), \
          "=r"((r)[24]), "=r"((r)[25]), "=r"((r)[26]), "=r"((r)[27]), \
          "=r"((r)[28]), "=r"((r)[29]), "=r"((r)[30]), "=r"((r)[31]) \
        : "r"(tmem_addr))

static constexpr uint64_t SMEM_DESC_BASE_SW128 =
    (uint64_t(2) << 61) | (uint64_t(1) << 46) | (uint64_t(64) << 32) | (uint64_t(1) << 16);
#define MAKE_SMEM_DESC(base_addr) (SMEM_DESC_BASE_SW128 | ((uint64_t)((base_addr) >> 4) & 0x3FFF))

#if HAS_TCGEN05
// cg2 TMA: both CTAs execute; complete_tx routes to the pair leader's barrier
// (bit 24 cleared = Sm100MmaPeerBitMask), data lands in the issuing CTA's SMEM.
#define TMA_LOAD_3D_CG2(smem_addr, map_ptr, cx, cy, mbar) \
    asm volatile("{\n\t.reg .b32 lb;\n\t" \
        "and.b32 lb, %5, 0xFEFFFFFF;\n\t" \
        "cp.async.bulk.tensor.3d.cta_group::2.shared::cluster.global.tile.mbarrier::complete_tx::bytes " \
        "[%0], [%1, {%2, %3, %4}], [lb];\n\t}" \
        :: "r"((uint32_t)(smem_addr)), "l"(map_ptr), "r"((int32_t)(cx)), \
           "r"((int32_t)(cy)), "r"((int32_t)0), "r"((uint32_t)(mbar)) : "memory")

__device__ __forceinline__ void mma_f16_ss_cg2(uint32_t d_tmem, uint64_t a_desc, uint64_t b_desc,
                                               uint32_t idesc, uint32_t enable_d) {
    asm volatile(
        "{\n\t.reg .pred p;\n\t"
        "setp.ne.u32 p, %5, 0;\n\t"
        "tcgen05.mma.cta_group::2.kind::f16 [%0], %1, %2, %3, {%4, %4, %4, %4, %4, %4, %4, %4}, p;\n\t}"
        :: "r"(d_tmem), "l"(a_desc), "l"(b_desc), "r"(idesc), "r"(0u), "r"(enable_d)
        : "memory");
}
#define TCGEN05_COMMIT_MC_CG2(mbar) \
    asm volatile("tcgen05.commit.cta_group::2.mbarrier::arrive::one.shared::cluster.multicast::cluster.b64 [%0], %1;" \
                 :: "r"((uint32_t)(mbar)), "h"((uint16_t)0x3) : "memory")
#endif

// ---------------------------------------------------------------------------
// Kernel 1: fp32 -> bf16 conversion (8 floats/thread: 2 x float4 -> 1 x uint4)
// ---------------------------------------------------------------------------
__global__ void convert_kernel(const float* __restrict__ hid, const float* __restrict__ w) {
    const size_t nh8 = (size_t)BT * HDIM / 8;
    const size_t nw8 = (size_t)VOCAB * HDIM / 8;
    const size_t total = nh8 + nw8;
    size_t stride = (size_t)gridDim.x * blockDim.x;
    for (size_t i = (size_t)blockIdx.x * blockDim.x + threadIdx.x; i < total; i += stride) {
        const float4* src;
        __nv_bfloat16* dst;
        size_t j;
        if (i < nh8) { src = (const float4*)hid; dst = g_hid_bf; j = i; }
        else         { src = (const float4*)w;   dst = g_w_bf;   j = i - nh8; }
        float4 v0 = src[j * 2];
        float4 v1 = src[j * 2 + 1];
        __nv_bfloat162 p0 = __floats2bfloat162_rn(v0.x, v0.y);
        __nv_bfloat162 p1 = __floats2bfloat162_rn(v0.z, v0.w);
        __nv_bfloat162 p2 = __floats2bfloat162_rn(v1.x, v1.y);
        __nv_bfloat162 p3 = __floats2bfloat162_rn(v1.z, v1.w);
        uint4 o;
        o.x = *(uint32_t*)&p0;
        o.y = *(uint32_t*)&p1;
        o.z = *(uint32_t*)&p2;
        o.w = *(uint32_t*)&p3;
        *(uint4*)(dst + j * 8) = o;
    }
}

// ---------------------------------------------------------------------------
// Kernel 2: cg2 TMA-fed tcgen05 GEMM, 256x512 pair tiles, depth-4 pipeline,
// fused CE epilogue. Per chunk each CTA TMA-loads its A half + 2 B boxes
// (tx -> leader's fill bar); leader MMAs and multicast-commits; refills are
// gated 3 chunks back so commit round-trips stay off the critical path.
// ---------------------------------------------------------------------------
__global__ void __launch_bounds__(128)
__cluster_dims__(2, 1, 1)
gemm_ce_kernel(const __grid_constant__ CUtensorMap tma_a,
               const __grid_constant__ CUtensorMap tma_b,
               const long long* __restrict__ targets) {
    extern __shared__ __align__(1024) char smem[];
    int tid = threadIdx.x;

    int pair = blockIdx.x >> 1;
    int n_tile = pair / M_PAIRS;           // consecutive pairs share B panel (L2)
    int m_pair = pair % M_PAIRS;
    int n0 = n_tile * TILE_N;
    int nvalid = (n_tile == N_TILES - 1) ? (VOCAB - n0) : TILE_N;   // 512 or 256

#if HAS_TCGEN05
    uint32_t rank = cluster_ctarank_u32();
    int m0_cta = m_pair * 256 + (int)rank * 128;
    uint32_t sb = smem_to_u32(smem);
    int wid = tid >> 5;
    const bool full = (nvalid == TILE_N);

    if (wid == 0) TCGEN05_ALLOC_CG2(sb + SM_TMEMPTR, 512);
    __syncthreads();
    uint32_t tmem;
    asm volatile("ld.shared.b32 %0, [%1];" : "=r"(tmem) : "r"(sb + SM_TMEMPTR));

    if (tid == 0) {
#pragma unroll
        for (int b = 0; b < DEPTH; b++) {
            MBARRIER_INIT(sb + SM_FBAR(b), 1);
            MBARRIER_INIT(sb + SM_MBAR(b), 1);
        }
    }
    __syncthreads();
    CLUSTER_SYNC();   // leader's bars must be live before peer TMA complete_tx

    if (tid == 0) {
        const uint32_t bytes = full ? (2u * (A_CHUNK_BYTES + 2 * B_BOX_BYTES))   // 98304
                                    : (2u * (A_CHUNK_BYTES + B_BOX_BYTES));      // 65536
        // prologue: chunks 0..3 into buffers 0..3
#pragma unroll
        for (int p = 0; p < DEPTH; p++) {
            uint32_t fbar = sb + SM_FBAR(p);
            uint32_t abuf = sb + SM_A + p * A_CHUNK_BYTES;
            uint32_t bbuf = sb + SM_B + p * (2 * B_BOX_BYTES);
            if (rank == 0) MBARRIER_EXPECT_TX(fbar, bytes);
            TMA_LOAD_3D_CG2(abuf, &tma_a, p * K_CHUNK, m0_cta, fbar);
            TMA_LOAD_3D_CG2(bbuf, &tma_b, p * K_CHUNK, n0 + (int)rank * 128, fbar);
            if (full)
                TMA_LOAD_3D_CG2(bbuf + B_BOX_BYTES, &tma_b, p * K_CHUNK,
                                n0 + 256 + (int)rank * 128, fbar);
        }

        int phf[DEPTH] = {0, 0, 0, 0};
        int phm[DEPTH] = {0, 0, 0, 0};
#pragma unroll 1
        for (int kc = 0; kc < N_KCHUNKS; kc++) {
            int buf = kc & (DEPTH - 1);
            if (rank == 0) {
                MBARRIER_WAIT_PARITY(sb + SM_FBAR(buf), phf[buf]);
                phf[buf] ^= 1;
                uint64_t ad  = MAKE_SMEM_DESC(sb + SM_A + buf * A_CHUNK_BYTES);
                uint64_t bd0 = MAKE_SMEM_DESC(sb + SM_B + buf * (2 * B_BOX_BYTES));
                uint64_t bd1 = bd0 + (B_BOX_BYTES >> 4);
#pragma unroll
                for (int s = 0; s < 4; s++) {
                    uint32_t en = (kc > 0 || s > 0) ? 1u : 0u;
                    mma_f16_ss_cg2(tmem, ad + s * 2, bd0 + s * 2, MMA_IDESC, en);
                    if (full)
                        mma_f16_ss_cg2(tmem + 256, ad + s * 2, bd1 + s * 2, MMA_IDESC, en);
                }
                TCGEN05_COMMIT_MC_CG2(sb + SM_MBAR(buf));
            }
            if (kc + DEPTH < N_KCHUNKS) {
                // refill buffer `buf` only after MMA(kc) released both CTAs' SMEM;
                // this gate is DEPTH-1 chunks ahead of the next consumer -> hidden.
                MBARRIER_WAIT_PARITY(sb + SM_MBAR(buf), phm[buf]);
                phm[buf] ^= 1;
                uint32_t fbar = sb + SM_FBAR(buf);
                uint32_t abuf = sb + SM_A + buf * A_CHUNK_BYTES;
                uint32_t bbuf = sb + SM_B + buf * (2 * B_BOX_BYTES);
                int k0 = (kc + DEPTH) * K_CHUNK;
                if (rank == 0) MBARRIER_EXPECT_TX(fbar, bytes);
                TMA_LOAD_3D_CG2(abuf, &tma_a, k0, m0_cta, fbar);
                TMA_LOAD_3D_CG2(bbuf, &tma_b, k0, n0 + (int)rank * 128, fbar);
                if (full)
                    TMA_LOAD_3D_CG2(bbuf + B_BOX_BYTES, &tma_b, k0,
                                    n0 + 256 + (int)rank * 128, fbar);
            }
        }
        // final completions: chunks 28..31 -> bars 0..3 (both CTAs)
#pragma unroll
        for (int b = 0; b < DEPTH; b++)
            MBARRIER_WAIT_PARITY(sb + SM_MBAR(b), phm[b]);
    }
    __syncthreads();
    TCGEN05_FENCE_AFTER();

    // Epilogue: this CTA's TMEM lanes = rows m_pair*256 + rank*128 + tid,
    // columns c map linearly to vocab n0 + c (B-split ordering).
    int row = m0_cta + tid;
    long long t = targets[row];
    float sum = 0.0f;
    float tval = 0.0f;
    int cmax = nvalid / 32;
#pragma unroll 1
    for (int c = 0; c < cmax; c++) {
        uint32_t regs[32];
        TCGEN05_LD_32X32B_X32(regs, tmem + c * 32);
        TCGEN05_WAIT_LD();
#pragma unroll
        for (int j = 0; j < 32; j++) {
            float v = __uint_as_float(regs[j]);
            sum += __expf(v);
            if ((long long)(n0 + c * 32 + j) == t) tval = v;
        }
    }
    TCGEN05_FENCE_BEFORE();
    g_partials[(size_t)n_tile * BT + row] = sum;
    if (t >= (long long)n0 && t < (long long)(n0 + nvalid)) g_tgt[row] = tval;

    __syncthreads();
    if (tid == 0) {
#pragma unroll
        for (int b = 0; b < DEPTH; b++) {
            MBARRIER_INVAL(sb + SM_FBAR(b));
            MBARRIER_INVAL(sb + SM_MBAR(b));
        }
    }
    __syncthreads();
    if (wid == 0) {
        TCGEN05_RELINQUISH_CG2();
        TCGEN05_DEALLOC_CG2(tmem, 512);
    }
    CLUSTER_SYNC();   // no exit while peer SMEM/TMEM may still be referenced

#else  // ------- non-sm_103a fallback (PTX-JIT path only) --------------------
    int rank = blockIdx.x & 1;
    int m0 = m_pair * 256 + rank * 128;
    __nv_bfloat16* As = (__nv_bfloat16*)smem;
    __nv_bfloat16* Bs = (__nv_bfloat16*)(smem + 16384);
    const __nv_bfloat16* Ag = g_hid_bf + (size_t)m0 * HDIM;

    long long t = targets[m0 + tid];
    float sum = 0.0f, tval = 0.0f;
    for (int cg = 0; cg < nvalid / 32; cg++) {
        float acc[32];
#pragma unroll
        for (int j = 0; j < 32; j++) acc[j] = 0.0f;
        const __nv_bfloat16* Bg = g_w_bf + (size_t)(n0 + cg * 32) * HDIM;
        for (int kc = 0; kc < N_KCHUNKS; kc++) {
            __syncthreads();
            int k0 = kc * K_CHUNK;
#pragma unroll
            for (int l = 0; l < 8; l++) {
                int i = tid + l * 128;
                int r2 = i >> 3, c = i & 7;
                *(uint4*)(As + r2 * 64 + c * 8) =
                    *(const uint4*)(Ag + (size_t)r2 * HDIM + k0 + c * 8);
            }
#pragma unroll
            for (int l = 0; l < 2; l++) {
                int i = tid + l * 128;
                int r2 = i >> 3, c = i & 7;
                *(uint4*)(Bs + r2 * 64 + c * 8) =
                    *(const uint4*)(Bg + (size_t)r2 * HDIM + k0 + c * 8);
            }
            __syncthreads();
            for (int k = 0; k < K_CHUNK; k++) {
                float a = __bfloat162float(As[tid * 64 + k]);
#pragma unroll
                for (int j = 0; j < 32; j++)
                    acc[j] += a * __bfloat162float(Bs[j * 64 + k]);
            }
        }
#pragma unroll
        for (int j = 0; j < 32; j++) {
            float v = acc[j];
            sum += __expf(v);
            if ((long long)(n0 + cg * 32 + j) == t) tval = v;
        }
    }
    g_partials[(size_t)n_tile * BT + m0 + tid] = sum;
    if (t >= (long long)n0 && t < (long long)(n0 + nvalid)) g_tgt[m0 + tid] = tval;
#endif
}

// ---------------------------------------------------------------------------
// Kernel 3a: per-row loss, whole-chip parallel, deterministic
// ---------------------------------------------------------------------------
__global__ void row_loss_kernel(const long long* __restrict__ targets) {
    __shared__ float sl[256];
    __shared__ int sc[256];
    int tid = threadIdx.x;
    int r = blockIdx.x * 256 + tid;

    float s = 0.0f;
#pragma unroll 7
    for (int nt = 0; nt < N_TILES; nt++) s += g_partials[(size_t)nt * BT + r];

    long long t = targets[r];
    bool valid = (t != IGNORE_INDEX);
    sl[tid] = valid ? (logf(s) - g_tgt[r]) : 0.0f;
    sc[tid] = valid ? 1 : 0;
    __syncthreads();
#pragma unroll
    for (int o = 128; o > 0; o >>= 1) {
        if (tid < o) { sl[tid] += sl[tid + o]; sc[tid] += sc[tid + o]; }
        __syncthreads();
    }
    if (tid == 0) { g_blocksum[blockIdx.x] = sl[0]; g_blockcnt[blockIdx.x] = sc[0]; }
}

// ---------------------------------------------------------------------------
// Kernel 3b: final scalar combine
// ---------------------------------------------------------------------------
__global__ void final_kernel(float* __restrict__ out) {
    if (threadIdx.x == 0) {
        float s = 0.0f;
        int c = 0;
#pragma unroll
        for (int b = 0; b < RL_BLOCKS; b++) { s += g_blocksum[b]; c += g_blockcnt[b]; }
        out[0] = s / (float)(c > 0 ? c : 1);
    }
}

// ---------------------------------------------------------------------------
// Host: tensor-map construction via driver entry point (no -lcuda needed)
// ---------------------------------------------------------------------------
typedef CUresult (*tmap_encode_fn)(
    CUtensorMap*, CUtensorMapDataType, cuuint32_t, void*,
    const cuuint64_t*, const cuuint64_t*, const cuuint32_t*, const cuuint32_t*,
    CUtensorMapInterleave, CUtensorMapSwizzle, CUtensorMapL2promotion,
    CUtensorMapFloatOOBfill);

extern "C" void kernel_launch(void* const* d_in, const int* in_sizes, int n_in,
                              void* d_out, int out_size) {
    const float* hidden = (const float*)d_in[0];
    const float* weight = (const float*)d_in[1];
    const long long* targets = (const long long*)d_in[2];
    float* out = (float*)d_out;

    cudaFuncSetAttribute(gemm_ce_kernel, cudaFuncAttributeMaxDynamicSharedMemorySize, SM_TOTAL);

    void* hid_bf_ptr = nullptr;
    void* w_bf_ptr = nullptr;
    cudaGetSymbolAddress(&hid_bf_ptr, g_hid_bf);
    cudaGetSymbolAddress(&w_bf_ptr, g_w_bf);

    tmap_encode_fn encode = nullptr;
    cudaDriverEntryPointQueryResult qres;
    cudaGetDriverEntryPoint("cuTensorMapEncodeTiled", (void**)&encode,
                            cudaEnableDefault, &qres);

    CUtensorMap tma_a, tma_b;
    {
        cuuint64_t dims[3] = {(cuuint64_t)HDIM, (cuuint64_t)BT, 1};
        cuuint64_t strides[2] = {(cuuint64_t)HDIM * 2, (cuuint64_t)HDIM * 2 * BT};
        cuuint32_t box[3] = {K_CHUNK, 128, 1};   // 128B rows (SW128), 128 rows
        cuuint32_t es[3] = {1, 1, 1};
        encode(&tma_a, CU_TENSOR_MAP_DATA_TYPE_BFLOAT16, 3, hid_bf_ptr,
               dims, strides, box, es,
               CU_TENSOR_MAP_INTERLEAVE_NONE, CU_TENSOR_MAP_SWIZZLE_128B,
               CU_TENSOR_MAP_L2_PROMOTION_L2_128B, CU_TENSOR_MAP_FLOAT_OOB_FILL_NONE);
    }
    {
        cuuint64_t dims[3] = {(cuuint64_t)HDIM, (cuuint64_t)VOCAB, 1};
        cuuint64_t strides[2] = {(cuuint64_t)HDIM * 2, (cuuint64_t)HDIM * 2 * VOCAB};
        cuuint32_t box[3] = {K_CHUNK, 128, 1};   // B loaded as 128-row boxes
        cuuint32_t es[3] = {1, 1, 1};
        encode(&tma_b, CU_TENSOR_MAP_DATA_TYPE_BFLOAT16, 3, w_bf_ptr,
               dims, strides, box, es,
               CU_TENSOR_MAP_INTERLEAVE_NONE, CU_TENSOR_MAP_SWIZZLE_128B,
               CU_TENSOR_MAP_L2_PROMOTION_L2_128B, CU_TENSOR_MAP_FLOAT_OOB_FILL_NONE);
    }

    convert_kernel<<<2048, 256>>>(hidden, weight);
    gemm_ce_kernel<<<M_PAIRS * N_TILES * 2, 128, SM_TOTAL>>>(tma_a, tma_b, targets);
    row_loss_kernel<<<RL_BLOCKS, 256>>>(targets);
    final_kernel<<<1, 32>>>(out);
}

// round 9
// speedup vs baseline: 1.0901x; 1.0901x over previous
#include <cuda_runtime.h>
#include <cuda.h>
#include <cuda_bf16.h>
#include <cstdint>

// ---------------------------------------------------------------------------
// Problem constants
// ---------------------------------------------------------------------------
#define BT 4096
#define HDIM 2048
#define VOCAB 32000
#define TILE_M 256                         // per CTA: two M=128 MMA halves
#define TILE_N 256
#define K_CHUNK 64
#define N_KCHUNKS (HDIM / K_CHUNK)         // 32
#define M_TILES (BT / TILE_M)              // 16
#define N_TILES (VOCAB / TILE_N)           // 125 (exact)
#define IGNORE_INDEX (-100LL)
#define RL_BLOCKS 16
#define DEPTH 3                            // pipeline stages

// idesc per M=128 x N=256 MMA: dtype=F32(1<<4), atype=BF16(1<<7),
// btype=BF16(1<<10), N/8<<17, M/16<<24   (identical to the R5/R6 winner)
#define MMA_IDESC ((1u << 4) | (1u << 7) | (1u << 10) | ((256 / 8) << 17) | ((128 / 16) << 24))

// SMEM layout: header, then DEPTH x (A 32KB), DEPTH x (B 32KB)
#define SM_TMEMPTR 0
#define SM_FBAR(i) (8 + 8 * (i))
#define SM_MBAR(i) (40 + 8 * (i))
#define A_CHUNK_BYTES (TILE_M * 128)       // 32768 (256 rows x 128B)
#define B_CHUNK_BYTES (TILE_N * 128)       // 32768
#define SM_A 1024
#define SM_B (1024 + DEPTH * A_CHUNK_BYTES)        // 99328
#define SM_TOTAL (SM_B + DEPTH * B_CHUNK_BYTES)    // 197632 (<227KB)

#define CHUNK_TX_BYTES (A_CHUNK_BYTES + B_CHUNK_BYTES)  // 65536

#if defined(__CUDA_ARCH_FEAT_SM103_ALL) || defined(__CUDA_ARCH_FEAT_SM100_ALL)
#define HAS_TCGEN05 1
#else
#define HAS_TCGEN05 0
#endif

// ---------------------------------------------------------------------------
// Device scratch
// ---------------------------------------------------------------------------
__device__ __nv_bfloat16 g_hid_bf[(size_t)BT * HDIM];
__device__ __nv_bfloat16 g_w_bf[(size_t)VOCAB * HDIM];
__device__ float g_partials[(size_t)N_TILES * BT];
__device__ float g_tgt[BT];
__device__ float g_blocksum[RL_BLOCKS];
__device__ int   g_blockcnt[RL_BLOCKS];

// ---------------------------------------------------------------------------
// PTX helpers
// ---------------------------------------------------------------------------
__device__ __forceinline__ uint32_t smem_to_u32(const void* p) {
    uint32_t a;
    asm("{ .reg .u64 t; cvta.to.shared.u64 t, %1; cvt.u32.u64 %0, t; }" : "=r"(a) : "l"(p));
    return a;
}
#define TCGEN05_ALLOC(smem_addr, nCols) \
    asm volatile("tcgen05.alloc.cta_group::1.sync.aligned.shared::cta.b32 [%0], %1;" \
                 :: "r"((uint32_t)(smem_addr)), "r"((uint32_t)(nCols)) : "memory")
#define TCGEN05_DEALLOC(tmem_addr, nCols) \
    asm volatile("tcgen05.dealloc.cta_group::1.sync.aligned.b32 %0, %1;" :: "r"(tmem_addr), "r"((uint32_t)(nCols)))
#define TCGEN05_RELINQUISH() \
    asm volatile("tcgen05.relinquish_alloc_permit.cta_group::1.sync.aligned;")
#define TCGEN05_COMMIT(mbar) \
    asm volatile("tcgen05.commit.cta_group::1.mbarrier::arrive::one.shared::cluster.b64 [%0];" \
                 :: "r"((uint32_t)(mbar)) : "memory")
#define TCGEN05_FENCE_AFTER() asm volatile("tcgen05.fence::after_thread_sync;" ::: "memory")
#define TCGEN05_FENCE_BEFORE() asm volatile("tcgen05.fence::before_thread_sync;" ::: "memory")
#define TCGEN05_WAIT_LD() asm volatile("tcgen05.wait::ld.sync.aligned;" ::: "memory")
#define MBARRIER_INIT(mbar, cnt) \
    asm volatile("mbarrier.init.shared.b64 [%0], %1;" :: "r"((uint32_t)(mbar)), "r"((uint32_t)(cnt)) : "memory")
#define MBARRIER_INVAL(mbar) \
    asm volatile("mbarrier.inval.shared.b64 [%0];" :: "r"((uint32_t)(mbar)) : "memory")
#define MBARRIER_EXPECT_TX(mbar, bytes) \
    asm volatile("mbarrier.arrive.expect_tx.shared.b64 _, [%0], %1;" \
                 :: "r"((uint32_t)(mbar)), "r"((uint32_t)(bytes)) : "memory")
#define MBARRIER_WAIT_PARITY(mbar, parity) do {                                           \
    uint32_t _m = (uint32_t)(mbar); uint32_t _p = (uint32_t)(parity); uint32_t _d;        \
    asm volatile("{\n\t.reg .pred p;\n\t"                                                 \
        "mbarrier.try_wait.parity.acquire.cta.shared::cta.b64 p, [%1], %2;\n\t"           \
        "selp.b32 %0, 1, 0, p;\n\t}" : "=r"(_d) : "r"(_m), "r"(_p) : "memory");           \
    if (!_d) {                                                                            \
        asm volatile("{\n\t.reg .pred P1;\n\t"                                            \
            "WAIT_LOOP_%=:\n\t"                                                           \
            "mbarrier.try_wait.parity.acquire.cta.shared::cta.b64 P1, [%0], %1, 0x989680;\n\t" \
            "@P1 bra.uni WAIT_DONE_%=;\n\t"                                               \
            "bra.uni WAIT_LOOP_%=;\n\t"                                                   \
            "WAIT_DONE_%=:\n\t}" :: "r"(_m), "r"(_p) : "memory");                         \
    }                                                                                     \
} while (0)
#define TMA_LOAD_2D(smem_addr, map_ptr, cx, cy, mbar) \
    asm volatile("cp.async.bulk.tensor.2d.shared::cta.global.tile.mbarrier::complete_tx::bytes " \
                 "[%0], [%1, {%2, %3}], [%4];" \
                 :: "r"((uint32_t)(smem_addr)), "l"(map_ptr), "r"((int32_t)(cx)), \
                    "r"((int32_t)(cy)), "r"((uint32_t)(mbar)) : "memory")
#define TCGEN05_LD_32X32B_X32(r, tmem_addr) \
    asm volatile( \
        "tcgen05.ld.sync.aligned.32x32b.x32.b32 " \
        "{%0, %1, %2, %3, %4, %5, %6, %7, " \
        " %8, %9, %10, %11, %12, %13, %14, %15, " \
        " %16, %17, %18, %19, %20, %21, %22, %23, " \
        " %24, %25, %26, %27, %28, %29, %30, %31}, [%32];" \
        : "=r"((r)[0]),  "=r"((r)[1]),  "=r"((r)[2]),  "=r"((r)[3]), \
          "=r"((r)[4]),  "=r"((r)[5]),  "=r"((r)[6]),  "=r"((r)[7]), \
          "=r"((r)[8]),  "=r"((r)[9]),  "=r"((r)[10]), "=r"((r)[11]), \
          "=r"((r)[12]), "=r"((r)[13]), "=r"((r)[14]), "=r"((r)[15]), \
          "=r"((r)[16]), "=r"((r)[17]), "=r"((r)[18]), "=r"((r)[19]), \
          "=r"((r)[20]), "=r"((r)[21]), "=r"((r)[22]), "=r"((r)[23]), \
          "=r"((r)[24]), "=r"((r)[25]), "=r"((r)[26]), "=r"((r)[27]), \
          "=r"((r)[28]), "=r"((r)[29]), "=r"((r)[30]), "=r"((r)[31]) \
        : "r"(tmem_addr))

static constexpr uint64_t SMEM_DESC_BASE_SW128 =
    (uint64_t(2) << 61) | (uint64_t(1) << 46) | (uint64_t(64) << 32) | (uint64_t(1) << 16);
#define MAKE_SMEM_DESC(base_addr) (SMEM_DESC_BASE_SW128 | ((uint64_t)((base_addr) >> 4) & 0x3FFF))

#if HAS_TCGEN05
__device__ __forceinline__ void mma_f16_ss(uint32_t d_tmem, uint64_t a_desc, uint64_t b_desc,
                                           uint32_t idesc, uint32_t enable_d) {
    asm volatile(
        "{\n\t.reg .pred p;\n\t"
        "setp.ne.u32 p, %5, 0;\n\t"
        "tcgen05.mma.cta_group::1.kind::f16 [%0], %1, %2, %3, {%4, %4, %4, %4}, p;\n\t}"
        :: "r"(d_tmem), "l"(a_desc), "l"(b_desc), "r"(idesc), "r"(0u), "r"(enable_d)
        : "memory");
}
#endif

// ---------------------------------------------------------------------------
// Kernel 1: fp32 -> bf16 conversion (8 floats/thread: 2 x float4 -> 1 x uint4)
// ---------------------------------------------------------------------------
__global__ void convert_kernel(const float* __restrict__ hid, const float* __restrict__ w) {
    const size_t nh8 = (size_t)BT * HDIM / 8;
    const size_t nw8 = (size_t)VOCAB * HDIM / 8;
    const size_t total = nh8 + nw8;
    size_t stride = (size_t)gridDim.x * blockDim.x;
    for (size_t i = (size_t)blockIdx.x * blockDim.x + threadIdx.x; i < total; i += stride) {
        const float4* src;
        __nv_bfloat16* dst;
        size_t j;
        if (i < nh8) { src = (const float4*)hid; dst = g_hid_bf; j = i; }
        else         { src = (const float4*)w;   dst = g_w_bf;   j = i - nh8; }
        float4 v0 = src[j * 2];
        float4 v1 = src[j * 2 + 1];
        __nv_bfloat162 p0 = __floats2bfloat162_rn(v0.x, v0.y);
        __nv_bfloat162 p1 = __floats2bfloat162_rn(v0.z, v0.w);
        __nv_bfloat162 p2 = __floats2bfloat162_rn(v1.x, v1.y);
        __nv_bfloat162 p3 = __floats2bfloat162_rn(v1.z, v1.w);
        uint4 o;
        o.x = *(uint32_t*)&p0;
        o.y = *(uint32_t*)&p1;
        o.z = *(uint32_t*)&p2;
        o.w = *(uint32_t*)&p3;
        *(uint4*)(dst + j * 8) = o;
    }
}

// ---------------------------------------------------------------------------
// Kernel 2: TMA-fed cg1 tcgen05 GEMM, 256x256 tiles (two M=128 accumulators
// in TMEM cols [0,256) and [256,512) sharing one B tile), depth-3 pipeline,
// fused CE epilogue. Single driver thread owns the pipeline.
// ---------------------------------------------------------------------------
__global__ void __launch_bounds__(128, 1)
gemm_ce_kernel(const __grid_constant__ CUtensorMap tma_a,
               const __grid_constant__ CUtensorMap tma_b,
               const long long* __restrict__ targets) {
    extern __shared__ __align__(1024) char smem[];
    int tid = threadIdx.x;

    // consecutive blocks share the same weight (N) panel -> L2 reuse in a wave
    int n_tile = blockIdx.x / M_TILES;
    int m_tile = blockIdx.x % M_TILES;
    int m0 = m_tile * TILE_M;
    int n0 = n_tile * TILE_N;

#if HAS_TCGEN05
    uint32_t sb = smem_to_u32(smem);
    int wid = tid >> 5;

    if (wid == 0) {
        TCGEN05_ALLOC(sb + SM_TMEMPTR, 512);
        TCGEN05_RELINQUISH();
    }
    __syncthreads();
    uint32_t tmem;
    asm volatile("ld.shared.b32 %0, [%1];" : "=r"(tmem) : "r"(sb + SM_TMEMPTR));

    if (tid == 0) {
#pragma unroll
        for (int b = 0; b < DEPTH; b++) {
            MBARRIER_INIT(sb + SM_FBAR(b), 1);
            MBARRIER_INIT(sb + SM_MBAR(b), 1);
        }
    }
    __syncthreads();

    if (tid == 0) {
        // prologue: chunks 0..DEPTH-1 into buffers 0..DEPTH-1
#pragma unroll
        for (int p = 0; p < DEPTH; p++) {
            uint32_t fbar = sb + SM_FBAR(p);
            MBARRIER_EXPECT_TX(fbar, CHUNK_TX_BYTES);
            TMA_LOAD_2D(sb + SM_A + p * A_CHUNK_BYTES, &tma_a, p * K_CHUNK, m0, fbar);
            TMA_LOAD_2D(sb + SM_B + p * B_CHUNK_BYTES, &tma_b, p * K_CHUNK, n0, fbar);
        }

        int phf[DEPTH] = {0, 0, 0};
        int phm[DEPTH] = {0, 0, 0};
        int buf = 0;
#pragma unroll 1
        for (int kc = 0; kc < N_KCHUNKS; kc++) {
            MBARRIER_WAIT_PARITY(sb + SM_FBAR(buf), phf[buf]);
            phf[buf] ^= 1;
            uint64_t ad0 = MAKE_SMEM_DESC(sb + SM_A + buf * A_CHUNK_BYTES);
            uint64_t ad1 = ad0 + ((128 * 128) >> 4);   // rows 128..255: +16KB
            uint64_t bd  = MAKE_SMEM_DESC(sb + SM_B + buf * B_CHUNK_BYTES);
#pragma unroll
            for (int s = 0; s < 4; s++) {              // 4 x K=16 per 64-col chunk
                uint32_t en = (kc > 0 || s > 0) ? 1u : 0u;
                mma_f16_ss(tmem,       ad0 + s * 2, bd + s * 2, MMA_IDESC, en);
                mma_f16_ss(tmem + 256, ad1 + s * 2, bd + s * 2, MMA_IDESC, en);
            }
            TCGEN05_COMMIT(sb + SM_MBAR(buf));

            if (kc + DEPTH < N_KCHUNKS) {
                // refill `buf` only after MMA(kc) released it — gate sits
                // DEPTH-1 chunks ahead of its next consumer, so it's hidden.
                MBARRIER_WAIT_PARITY(sb + SM_MBAR(buf), phm[buf]);
                phm[buf] ^= 1;
                uint32_t fbar = sb + SM_FBAR(buf);
                int k0 = (kc + DEPTH) * K_CHUNK;
                MBARRIER_EXPECT_TX(fbar, CHUNK_TX_BYTES);
                TMA_LOAD_2D(sb + SM_A + buf * A_CHUNK_BYTES, &tma_a, k0, m0, fbar);
                TMA_LOAD_2D(sb + SM_B + buf * B_CHUNK_BYTES, &tma_b, k0, n0, fbar);
            }
            if (++buf == DEPTH) buf = 0;
        }
        // outstanding MMA completions on all buffers
#pragma unroll
        for (int b = 0; b < DEPTH; b++)
            MBARRIER_WAIT_PARITY(sb + SM_MBAR(b), phm[b]);
    }
    __syncthreads();
    TCGEN05_FENCE_AFTER();

    // Epilogue: thread tid covers two rows:
    //   row0 = m0 + tid        from accumulator 0 (tmem cols 0..255)
    //   row1 = m0 + 128 + tid  from accumulator 1 (tmem cols 256..511)
    {
        int row0 = m0 + tid;
        long long t0 = targets[row0];
        float sum0 = 0.0f, tval0 = 0.0f;
#pragma unroll 1
        for (int c = 0; c < 8; c++) {
            uint32_t regs[32];
            TCGEN05_LD_32X32B_X32(regs, tmem + c * 32);
            TCGEN05_WAIT_LD();
#pragma unroll
            for (int j = 0; j < 32; j++) {
                float v = __uint_as_float(regs[j]);
                sum0 += __expf(v);
                if ((long long)(n0 + c * 32 + j) == t0) tval0 = v;
            }
        }
        g_partials[(size_t)n_tile * BT + row0] = sum0;
        if (t0 >= (long long)n0 && t0 < (long long)(n0 + TILE_N)) g_tgt[row0] = tval0;

        int row1 = m0 + 128 + tid;
        long long t1 = targets[row1];
        float sum1 = 0.0f, tval1 = 0.0f;
#pragma unroll 1
        for (int c = 0; c < 8; c++) {
            uint32_t regs[32];
            TCGEN05_LD_32X32B_X32(regs, tmem + 256 + c * 32);
            TCGEN05_WAIT_LD();
#pragma unroll
            for (int j = 0; j < 32; j++) {
                float v = __uint_as_float(regs[j]);
                sum1 += __expf(v);
                if ((long long)(n0 + c * 32 + j) == t1) tval1 = v;
            }
        }
        g_partials[(size_t)n_tile * BT + row1] = sum1;
        if (t1 >= (long long)n0 && t1 < (long long)(n0 + TILE_N)) g_tgt[row1] = tval1;
    }
    TCGEN05_FENCE_BEFORE();

    __syncthreads();
    if (tid == 0) {
#pragma unroll
        for (int b = 0; b < DEPTH; b++) {
            MBARRIER_INVAL(sb + SM_FBAR(b));
            MBARRIER_INVAL(sb + SM_MBAR(b));
        }
    }
    __syncthreads();
    if (wid == 0) TCGEN05_DEALLOC(tmem, 512);

#else  // ------- non-sm_103a fallback (PTX-JIT path only) --------------------
    __nv_bfloat16* As = (__nv_bfloat16*)smem;
    __nv_bfloat16* Bs = (__nv_bfloat16*)(smem + 16384);

    for (int mh = 0; mh < 2; mh++) {
        int m0h = m0 + mh * 128;
        const __nv_bfloat16* Ag = g_hid_bf + (size_t)m0h * HDIM;
        long long t = targets[m0h + tid];
        float sum = 0.0f, tval = 0.0f;
        for (int cg = 0; cg < TILE_N / 32; cg++) {
            float acc[32];
#pragma unroll
            for (int j = 0; j < 32; j++) acc[j] = 0.0f;
            const __nv_bfloat16* Bg = g_w_bf + (size_t)(n0 + cg * 32) * HDIM;
            for (int kc = 0; kc < N_KCHUNKS; kc++) {
                __syncthreads();
                int k0 = kc * K_CHUNK;
#pragma unroll
                for (int l = 0; l < 8; l++) {
                    int i = tid + l * 128;
                    int r2 = i >> 3, c = i & 7;
                    *(uint4*)(As + r2 * 64 + c * 8) =
                        *(const uint4*)(Ag + (size_t)r2 * HDIM + k0 + c * 8);
                }
#pragma unroll
                for (int l = 0; l < 2; l++) {
                    int i = tid + l * 128;
                    int r2 = i >> 3, c = i & 7;
                    *(uint4*)(Bs + r2 * 64 + c * 8) =
                        *(const uint4*)(Bg + (size_t)r2 * HDIM + k0 + c * 8);
                }
                __syncthreads();
                for (int k = 0; k < K_CHUNK; k++) {
                    float a = __bfloat162float(As[tid * 64 + k]);
#pragma unroll
                    for (int j = 0; j < 32; j++)
                        acc[j] += a * __bfloat162float(Bs[j * 64 + k]);
                }
            }
#pragma unroll
            for (int j = 0; j < 32; j++) {
                float v = acc[j];
                sum += __expf(v);
                if ((long long)(n0 + cg * 32 + j) == t) tval = v;
            }
        }
        g_partials[(size_t)n_tile * BT + m0h + tid] = sum;
        if (t >= (long long)n0 && t < (long long)(n0 + TILE_N)) g_tgt[m0h + tid] = tval;
        __syncthreads();
    }
#endif
}

// ---------------------------------------------------------------------------
// Kernel 3a: per-row loss, whole-chip parallel, deterministic
// ---------------------------------------------------------------------------
__global__ void row_loss_kernel(const long long* __restrict__ targets) {
    __shared__ float sl[256];
    __shared__ int sc[256];
    int tid = threadIdx.x;
    int r = blockIdx.x * 256 + tid;

    float s = 0.0f;
#pragma unroll 5
    for (int nt = 0; nt < N_TILES; nt++) s += g_partials[(size_t)nt * BT + r];

    long long t = targets[r];
    bool valid = (t != IGNORE_INDEX);
    sl[tid] = valid ? (logf(s) - g_tgt[r]) : 0.0f;
    sc[tid] = valid ? 1 : 0;
    __syncthreads();
#pragma unroll
    for (int o = 128; o > 0; o >>= 1) {
        if (tid < o) { sl[tid] += sl[tid + o]; sc[tid] += sc[tid + o]; }
        __syncthreads();
    }
    if (tid == 0) { g_blocksum[blockIdx.x] = sl[0]; g_blockcnt[blockIdx.x] = sc[0]; }
}

// ---------------------------------------------------------------------------
// Kernel 3b: final scalar combine
// ---------------------------------------------------------------------------
__global__ void final_kernel(float* __restrict__ out) {
    if (threadIdx.x == 0) {
        float s = 0.0f;
        int c = 0;
#pragma unroll
        for (int b = 0; b < RL_BLOCKS; b++) { s += g_blocksum[b]; c += g_blockcnt[b]; }
        out[0] = s / (float)(c > 0 ? c : 1);
    }
}

// ---------------------------------------------------------------------------
// Host: tensor-map construction via driver entry point (no -lcuda needed)
// ---------------------------------------------------------------------------
typedef CUresult (*tmap_encode_fn)(
    CUtensorMap*, CUtensorMapDataType, cuuint32_t, void*,
    const cuuint64_t*, const cuuint64_t*, const cuuint32_t*, const cuuint32_t*,
    CUtensorMapInterleave, CUtensorMapSwizzle, CUtensorMapL2promotion,
    CUtensorMapFloatOOBfill);

extern "C" void kernel_launch(void* const* d_in, const int* in_sizes, int n_in,
                              void* d_out, int out_size) {
    const float* hidden = (const float*)d_in[0];
    const float* weight = (const float*)d_in[1];
    const long long* targets = (const long long*)d_in[2];
    float* out = (float*)d_out;

    cudaFuncSetAttribute(gemm_ce_kernel, cudaFuncAttributeMaxDynamicSharedMemorySize, SM_TOTAL);

    void* hid_bf_ptr = nullptr;
    void* w_bf_ptr = nullptr;
    cudaGetSymbolAddress(&hid_bf_ptr, g_hid_bf);
    cudaGetSymbolAddress(&w_bf_ptr, g_w_bf);

    tmap_encode_fn encode = nullptr;
    cudaDriverEntryPointQueryResult qres;
    cudaGetDriverEntryPoint("cuTensorMapEncodeTiled", (void**)&encode,
                            cudaEnableDefault, &qres);

    CUtensorMap tma_a, tma_b;
    {
        cuuint64_t dims[2] = {(cuuint64_t)HDIM, (cuuint64_t)BT};
        cuuint64_t strides[1] = {(cuuint64_t)HDIM * 2};
        cuuint32_t box[2] = {K_CHUNK, TILE_M};   // 128B rows (SW128), 256 rows
        cuuint32_t es[2] = {1, 1};
        encode(&tma_a, CU_TENSOR_MAP_DATA_TYPE_BFLOAT16, 2, hid_bf_ptr,
               dims, strides, box, es,
               CU_TENSOR_MAP_INTERLEAVE_NONE, CU_TENSOR_MAP_SWIZZLE_128B,
               CU_TENSOR_MAP_L2_PROMOTION_L2_128B, CU_TENSOR_MAP_FLOAT_OOB_FILL_NONE);
    }
    {
        cuuint64_t dims[2] = {(cuuint64_t)HDIM, (cuuint64_t)VOCAB};
        cuuint64_t strides[1] = {(cuuint64_t)HDIM * 2};
        cuuint32_t box[2] = {K_CHUNK, TILE_N};   // 256-row B boxes
        cuuint32_t es[2] = {1, 1};
        encode(&tma_b, CU_TENSOR_MAP_DATA_TYPE_BFLOAT16, 2, w_bf_ptr,
               dims, strides, box, es,
               CU_TENSOR_MAP_INTERLEAVE_NONE, CU_TENSOR_MAP_SWIZZLE_128B,
               CU_TENSOR_MAP_L2_PROMOTION_L2_128B, CU_TENSOR_MAP_FLOAT_OOB_FILL_NONE);
    }

    convert_kernel<<<2048, 256>>>(hidden, weight);
    gemm_ce_kernel<<<M_TILES * N_TILES, 128, SM_TOTAL>>>(tma_a, tma_b, targets);
    row_loss_kernel<<<RL_BLOCKS, 256>>>(targets);
    final_kernel<<<1, 32>>>(out);
}